// round 4
// baseline (speedup 1.0000x reference)
#include <cuda_runtime.h>
#include <math.h>
#include <stdint.h>

#define E 8
#define D 1024
#define NMAX 4096
#define CAP 4096

#define BM 128
#define BN 128
#define KC 32              // K per stage
#define NSTAGE (D / KC)    // 32
#define LDS_PAD 36         // floats per smem row (conflict-free)
#define STG_FLOATS (2 * BM * LDS_PAD)      // A + B per stage = 9216
#define SMEM_BYTES (3 * STG_FLOATS * 4)    // 110592

// ---------------- scratch (device globals; no runtime allocation) ----------------
__device__ float g_H[(size_t)E * CAP * D];
__device__ float g_O[(size_t)E * CAP * D];
__device__ int   g_cnt[E];
__device__ int   g_tok[E * CAP];
__device__ int   g_slot[NMAX * 2];
__device__ float g_wgt[NMAX * 2];

// ---------------- helpers ----------------
__device__ __forceinline__ uint32_t smem_u32(const void* p) {
    uint32_t a;
    asm("{ .reg .u64 t; cvta.to.shared.u64 t, %1; cvt.u32.u64 %0, t; }" : "=r"(a) : "l"(p));
    return a;
}
__device__ __forceinline__ void cp16(uint32_t s, const void* g) {
    asm volatile("cp.async.cg.shared.global [%0], [%1], 16;" :: "r"(s), "l"(g));
}
__device__ __forceinline__ uint32_t cvt_tf32(float v) {
    uint32_t r;
    asm("cvt.rna.tf32.f32 %0, %1;" : "=r"(r) : "f"(v));
    return r;
}
__device__ __forceinline__ void mma_tf32(float* c, const uint32_t* a, const uint32_t* b) {
    asm volatile(
        "mma.sync.aligned.m16n8k8.row.col.f32.tf32.tf32.f32 "
        "{%0,%1,%2,%3}, {%4,%5,%6,%7}, {%8,%9}, {%0,%1,%2,%3};"
        : "+f"(c[0]), "+f"(c[1]), "+f"(c[2]), "+f"(c[3])
        : "r"(a[0]), "r"(a[1]), "r"(a[2]), "r"(a[3]), "r"(b[0]), "r"(b[1]));
}

__global__ void zero_counts_kernel() {
    if (threadIdx.x < E) g_cnt[threadIdx.x] = 0;
}

// ---------------- gating ----------------
__global__ void gate_kernel(const float* __restrict__ x,
                            const float* __restrict__ gW,
                            const float* __restrict__ gb,
                            float* __restrict__ gate_prob_out,
                            int N)
{
    int token = blockIdx.x;
    if (token >= N) return;

    __shared__ float sx[D];
    __shared__ float slog[E];

    const float* xr = x + (size_t)token * D;
    for (int i = threadIdx.x; i < D; i += blockDim.x) sx[i] = xr[i];
    __syncthreads();

    int w = threadIdx.x >> 5, lane = threadIdx.x & 31;
    float s = 0.f;
    const float* wr = gW + w * D;
    for (int k = lane; k < D; k += 32) s += sx[k] * wr[k];
    #pragma unroll
    for (int o = 16; o; o >>= 1) s += __shfl_xor_sync(0xffffffffu, s, o);
    if (lane == 0) slog[w] = s + gb[w];
    __syncthreads();

    if (threadIdx.x == 0) {
        float p[E];
        float mx = -1e30f;
        #pragma unroll
        for (int e = 0; e < E; e++) mx = fmaxf(mx, slog[e]);
        float sum = 0.f;
        #pragma unroll
        for (int e = 0; e < E; e++) { p[e] = expf(slog[e] - mx); sum += p[e]; }
        float inv = 1.f / sum;

        int i0 = 0; float p0 = -1.f;
        #pragma unroll
        for (int e = 0; e < E; e++) {
            p[e] *= inv;
            gate_prob_out[(size_t)token * E + e] = p[e];
            if (p[e] > p0) { p0 = p[e]; i0 = e; }
        }
        int i1 = -1; float p1 = -1.f;
        #pragma unroll
        for (int e = 0; e < E; e++)
            if (e != i0 && p[e] > p1) { p1 = p[e]; i1 = e; }

        float e1 = expf(p1 - p0);
        float w0 = 1.f / (1.f + e1);
        float w1 = e1 / (1.f + e1);

        int pos0 = atomicAdd(&g_cnt[i0], 1);
        int pos1 = atomicAdd(&g_cnt[i1], 1);
        g_tok[i0 * CAP + pos0] = token;
        g_tok[i1 * CAP + pos1] = token;
        g_slot[token * 2 + 0] = i0 * CAP + pos0;
        g_slot[token * 2 + 1] = i1 * CAP + pos1;
        g_wgt[token * 2 + 0] = w0;
        g_wgt[token * 2 + 1] = w1;
    }
}

// ---------------- expert GEMM via mma.sync tf32 (64x64 warp tiles) ----------------
// C[m,n] = act(sum_k A[m,k] * W[n,k] + bias[n])
// mode 0: A = gathered x rows -> g_H (relu, b1)
// mode 1: A = g_H rows        -> g_O (b2)
__global__ __launch_bounds__(128, 2)
void expert_gemm_mma(const float* __restrict__ x,
                     const float* __restrict__ W,
                     const float* __restrict__ bias,
                     int mode)
{
    int e  = blockIdx.z;
    int ne = g_cnt[e];
    int m0 = blockIdx.x * BM;
    if (m0 >= ne) return;
    int n0 = blockIdx.y * BN;

    extern __shared__ float sm[];
    uint32_t smb = smem_u32(sm);

    int tid = threadIdx.x;   // 0..127; also the loader row

    // loader pointers: A row `tid`, B row (n) `tid`
    const float* Aptr;
    if (mode == 0) {
        int tok = (m0 + tid < ne) ? g_tok[e * CAP + m0 + tid] : 0;
        Aptr = x + (size_t)tok * D;
    } else {
        Aptr = g_H + ((size_t)e * CAP + m0 + tid) * D;
    }
    const float* Bptr = W + ((size_t)e * D + n0 + tid) * D;

    uint32_t a_sm = smb + (uint32_t)(tid * LDS_PAD) * 4u;
    uint32_t b_sm = a_sm + (uint32_t)(BM * LDS_PAD) * 4u;

    #define LOAD_STAGE(buf, k0) do {                                       \
        uint32_t _ab = a_sm + (uint32_t)(buf) * (STG_FLOATS * 4);           \
        uint32_t _bb = b_sm + (uint32_t)(buf) * (STG_FLOATS * 4);           \
        const float* _ag = Aptr + (k0);                                     \
        const float* _bg = Bptr + (k0);                                     \
        _Pragma("unroll")                                                   \
        for (int _c = 0; _c < 8; _c++) {                                    \
            cp16(_ab + _c * 16u, _ag + _c * 4);                             \
            cp16(_bb + _c * 16u, _bg + _c * 4);                             \
        }                                                                   \
        asm volatile("cp.async.commit_group;" ::: "memory");                \
    } while (0)

    LOAD_STAGE(0, 0);
    LOAD_STAGE(1, KC);

    int wid = tid >> 5, lane = tid & 31;
    int g  = lane >> 2, tg = lane & 3;
    int wm = (wid >> 1) * 64;       // 2 warps in m
    int wn = (wid & 1) * 64;        // 2 warps in n

    float acc[4][8][4];
    #pragma unroll
    for (int mt = 0; mt < 4; mt++)
        #pragma unroll
        for (int nt = 0; nt < 8; nt++)
            #pragma unroll
            for (int i = 0; i < 4; i++) acc[mt][nt][i] = 0.f;

    #pragma unroll 1
    for (int s = 0; s < NSTAGE; s++) {
        if (s < NSTAGE - 1) asm volatile("cp.async.wait_group 1;" ::: "memory");
        else                asm volatile("cp.async.wait_group 0;" ::: "memory");
        __syncthreads();

        if (s + 2 < NSTAGE) LOAD_STAGE((s + 2) % 3, (s + 2) * KC);

        const float* As = sm + (s % 3) * STG_FLOATS;
        const float* Bs = As + BM * LDS_PAD;

        #pragma unroll
        for (int kk = 0; kk < 4; kk++) {
            uint32_t a[4][4], b[8][2];
            #pragma unroll
            for (int mt = 0; mt < 4; mt++) {
                const float* ap = As + (wm + mt * 16 + g) * LDS_PAD + kk * 8 + tg;
                a[mt][0] = cvt_tf32(ap[0]);
                a[mt][1] = cvt_tf32(ap[8 * LDS_PAD]);
                a[mt][2] = cvt_tf32(ap[4]);
                a[mt][3] = cvt_tf32(ap[8 * LDS_PAD + 4]);
            }
            #pragma unroll
            for (int nt = 0; nt < 8; nt++) {
                const float* bp = Bs + (wn + nt * 8 + g) * LDS_PAD + kk * 8 + tg;
                b[nt][0] = cvt_tf32(bp[0]);
                b[nt][1] = cvt_tf32(bp[4]);
            }
            #pragma unroll
            for (int mt = 0; mt < 4; mt++)
                #pragma unroll
                for (int nt = 0; nt < 8; nt++)
                    mma_tf32(acc[mt][nt], a[mt], b[nt]);
        }
    }

    // ---------------- epilogue ----------------
    const float* brow = bias + (size_t)e * D + n0;
    float* Cb = (mode == 0) ? g_H : g_O;

    #pragma unroll
    for (int mt = 0; mt < 4; mt++) {
        #pragma unroll
        for (int rr = 0; rr < 2; rr++) {
            int m = m0 + wm + mt * 16 + rr * 8 + g;
            if (m >= ne) continue;
            float* crow = Cb + ((size_t)e * CAP + m) * D + n0;
            #pragma unroll
            for (int nt = 0; nt < 8; nt++) {
                int col = wn + nt * 8 + tg * 2;
                float v0 = acc[mt][nt][rr * 2 + 0] + brow[col];
                float v1 = acc[mt][nt][rr * 2 + 1] + brow[col + 1];
                if (mode == 0) { v0 = fmaxf(v0, 0.f); v1 = fmaxf(v1, 0.f); }
                float2 v = make_float2(v0, v1);
                *(float2*)(crow + col) = v;
            }
        }
    }
}

// ---------------- combine ----------------
__global__ void combine_kernel(float* __restrict__ y, int N)
{
    int token = blockIdx.x;
    if (token >= N) return;
    int   s0 = g_slot[token * 2 + 0];
    int   s1 = g_slot[token * 2 + 1];
    float w0 = g_wgt[token * 2 + 0];
    float w1 = g_wgt[token * 2 + 1];
    const float* o0 = g_O + (size_t)s0 * D;
    const float* o1 = g_O + (size_t)s1 * D;
    float* yr = y + (size_t)token * D;
    for (int i = threadIdx.x; i < D; i += blockDim.x)
        yr[i] = w0 * o0[i] + w1 * o1[i];
}

extern "C" void kernel_launch(void* const* d_in, const int* in_sizes, int n_in,
                              void* d_out, int out_size)
{
    const float* x  = (const float*)d_in[0];
    const float* gW = (const float*)d_in[1];
    const float* gb = (const float*)d_in[2];
    const float* w1 = (const float*)d_in[3];
    const float* b1 = (const float*)d_in[4];
    const float* w2 = (const float*)d_in[5];
    const float* b2 = (const float*)d_in[6];

    int N = in_sizes[0] / D;   // 4096

    float* y         = (float*)d_out;
    float* gate_prob = (float*)d_out + (size_t)N * D;

    static int smem_set = 0;
    if (!smem_set) {
        cudaFuncSetAttribute(expert_gemm_mma,
                             cudaFuncAttributeMaxDynamicSharedMemorySize, SMEM_BYTES);
        smem_set = 1;
    }

    zero_counts_kernel<<<1, 32>>>();
    gate_kernel<<<N, 256>>>(x, gW, gb, gate_prob, N);

    dim3 grid(NMAX / BM, D / BN, E);   // 32 x 8 x 8, inactive tiles exit early
    expert_gemm_mma<<<grid, 128, SMEM_BYTES>>>(x, w1, b1, 0);
    expert_gemm_mma<<<grid, 128, SMEM_BYTES>>>(x, w2, b2, 1);

    combine_kernel<<<N, 256>>>(y, N);
}

// round 6
// speedup vs baseline: 1.1539x; 1.1539x over previous
#include <cuda_runtime.h>
#include <math.h>
#include <stdint.h>

#define E 8
#define D 1024
#define NMAX 4096
#define CAP 4096

#define BM 128
#define BN 128
#define KC 32              // K per stage
#define NSTAGE (D / KC)    // 32
#define LDS_PAD 36         // floats per smem row (conflict-free)
#define STG_FLOATS (2 * BM * LDS_PAD)      // A + B per stage = 9216
#define SMEM_BYTES (3 * STG_FLOATS * 4)    // 110592

// ---------------- scratch (device globals; no runtime allocation) ----------------
__device__ float g_H[(size_t)E * CAP * D];
__device__ float g_O[(size_t)E * CAP * D];
__device__ float g_xr[(size_t)NMAX * D];       // tf32-rounded x
__device__ float g_W1r[(size_t)E * D * D];     // tf32-rounded w1
__device__ float g_W2r[(size_t)E * D * D];     // tf32-rounded w2
__device__ int   g_cnt[E];
__device__ int   g_tok[E * CAP];
__device__ int   g_slot[NMAX * 2];
__device__ float g_wgt[NMAX * 2];

// ---------------- helpers ----------------
__device__ __forceinline__ uint32_t smem_u32(const void* p) {
    uint32_t a;
    asm("{ .reg .u64 t; cvta.to.shared.u64 t, %1; cvt.u32.u64 %0, t; }" : "=r"(a) : "l"(p));
    return a;
}
__device__ __forceinline__ void cp16(uint32_t s, const void* g) {
    asm volatile("cp.async.cg.shared.global [%0], [%1], 16;" :: "r"(s), "l"(g));
}
__device__ __forceinline__ float round_tf32(float v) {
    uint32_t r;
    asm("cvt.rna.tf32.f32 %0, %1;" : "=r"(r) : "f"(v));
    return __uint_as_float(r);
}
__device__ __forceinline__ void mma_tf32(float* c, const uint32_t* a, const uint32_t* b) {
    asm volatile(
        "mma.sync.aligned.m16n8k8.row.col.f32.tf32.tf32.f32 "
        "{%0,%1,%2,%3}, {%4,%5,%6,%7}, {%8,%9}, {%0,%1,%2,%3};"
        : "+f"(c[0]), "+f"(c[1]), "+f"(c[2]), "+f"(c[3])
        : "r"(a[0]), "r"(a[1]), "r"(a[2]), "r"(a[3]), "r"(b[0]), "r"(b[1]));
}

__global__ void zero_counts_kernel() {
    if (threadIdx.x < E) g_cnt[threadIdx.x] = 0;
}

// ---------------- round weights to tf32 (w1 -> g_W1r, w2 -> g_W2r) ----------------
__global__ void round_w_kernel(const float* __restrict__ w1,
                               const float* __restrict__ w2)
{
    size_t n = (size_t)E * D * D / 4;       // in float4
    size_t i = (size_t)blockIdx.x * blockDim.x + threadIdx.x;
    size_t stride = (size_t)gridDim.x * blockDim.x;
    for (; i < n; i += stride) {
        float4 v1 = ((const float4*)w1)[i];
        v1.x = round_tf32(v1.x); v1.y = round_tf32(v1.y);
        v1.z = round_tf32(v1.z); v1.w = round_tf32(v1.w);
        ((float4*)g_W1r)[i] = v1;
        float4 v2 = ((const float4*)w2)[i];
        v2.x = round_tf32(v2.x); v2.y = round_tf32(v2.y);
        v2.z = round_tf32(v2.z); v2.w = round_tf32(v2.w);
        ((float4*)g_W2r)[i] = v2;
    }
}

// ---------------- gating (also emits tf32-rounded x) ----------------
__global__ void gate_kernel(const float* __restrict__ x,
                            const float* __restrict__ gW,
                            const float* __restrict__ gb,
                            float* __restrict__ gate_prob_out,
                            int N)
{
    int token = blockIdx.x;
    if (token >= N) return;

    __shared__ float sx[D];
    __shared__ float slog[E];

    const float* xr = x + (size_t)token * D;
    float* xout = g_xr + (size_t)token * D;
    for (int i = threadIdx.x; i < D; i += blockDim.x) {
        float v = xr[i];
        sx[i] = v;
        xout[i] = round_tf32(v);
    }
    __syncthreads();

    int w = threadIdx.x >> 5, lane = threadIdx.x & 31;
    float s = 0.f;
    const float* wr = gW + w * D;
    for (int k = lane; k < D; k += 32) s += sx[k] * wr[k];
    #pragma unroll
    for (int o = 16; o; o >>= 1) s += __shfl_xor_sync(0xffffffffu, s, o);
    if (lane == 0) slog[w] = s + gb[w];
    __syncthreads();

    if (threadIdx.x == 0) {
        float p[E];
        float mx = -1e30f;
        #pragma unroll
        for (int e = 0; e < E; e++) mx = fmaxf(mx, slog[e]);
        float sum = 0.f;
        #pragma unroll
        for (int e = 0; e < E; e++) { p[e] = expf(slog[e] - mx); sum += p[e]; }
        float inv = 1.f / sum;

        int i0 = 0; float p0 = -1.f;
        #pragma unroll
        for (int e = 0; e < E; e++) {
            p[e] *= inv;
            gate_prob_out[(size_t)token * E + e] = p[e];
            if (p[e] > p0) { p0 = p[e]; i0 = e; }
        }
        int i1 = -1; float p1 = -1.f;
        #pragma unroll
        for (int e = 0; e < E; e++)
            if (e != i0 && p[e] > p1) { p1 = p[e]; i1 = e; }

        float e1 = expf(p1 - p0);
        float w0 = 1.f / (1.f + e1);
        float w1 = e1 / (1.f + e1);

        int pos0 = atomicAdd(&g_cnt[i0], 1);
        int pos1 = atomicAdd(&g_cnt[i1], 1);
        g_tok[i0 * CAP + pos0] = token;
        g_tok[i1 * CAP + pos1] = token;
        g_slot[token * 2 + 0] = i0 * CAP + pos0;
        g_slot[token * 2 + 1] = i1 * CAP + pos1;
        g_wgt[token * 2 + 0] = w0;
        g_wgt[token * 2 + 1] = w1;
    }
}

// ---------------- expert GEMM via mma.sync tf32 (inputs pre-rounded) ----------------
// mode 0: A = gathered g_xr rows, W = g_W1r -> g_H (relu, b1, tf32-rounded store)
// mode 1: A = g_H rows,           W = g_W2r -> g_O (b2, full fp32 store)
__global__ __launch_bounds__(256, 2)
void expert_gemm_mma(const float* __restrict__ bias, int mode)
{
    int e  = blockIdx.z;
    int ne = g_cnt[e];
    int m0 = blockIdx.x * BM;
    if (m0 >= ne) return;
    int n0 = blockIdx.y * BN;

    extern __shared__ float sm[];
    uint32_t smb = smem_u32(sm);

    int tid  = threadIdx.x;
    int row  = tid >> 1;        // 0..127
    int half = tid & 1;

    const float* W = (mode == 0) ? g_W1r : g_W2r;   // device-side symbol ref (fixes R5 bug)

    const float* Aptr;
    if (mode == 0) {
        int tok = (m0 + row < ne) ? g_tok[e * CAP + m0 + row] : 0;
        Aptr = g_xr + (size_t)tok * D;
    } else {
        Aptr = g_H + ((size_t)e * CAP + m0 + row) * D;
    }
    const float* Bptr = W + ((size_t)e * D + n0 + row) * D;

    uint32_t a_sm = smb + (uint32_t)(row * LDS_PAD + half * 16) * 4u;
    uint32_t b_sm = a_sm + (uint32_t)(BM * LDS_PAD) * 4u;

    #define LOAD_STAGE(buf, k0) do {                                      \
        uint32_t _ab = a_sm + (uint32_t)(buf) * (STG_FLOATS * 4);          \
        uint32_t _bb = b_sm + (uint32_t)(buf) * (STG_FLOATS * 4);          \
        const float* _ag = Aptr + (k0) + half * 16;                        \
        const float* _bg = Bptr + (k0) + half * 16;                        \
        cp16(_ab,      _ag);      cp16(_bb,      _bg);                     \
        cp16(_ab + 16, _ag + 4);  cp16(_bb + 16, _bg + 4);                 \
        cp16(_ab + 32, _ag + 8);  cp16(_bb + 32, _bg + 8);                 \
        cp16(_ab + 48, _ag + 12); cp16(_bb + 48, _bg + 12);                \
        asm volatile("cp.async.commit_group;" ::: "memory");               \
    } while (0)

    LOAD_STAGE(0, 0);
    LOAD_STAGE(1, KC);

    int wid = tid >> 5, lane = tid & 31;
    int g  = lane >> 2, tg = lane & 3;
    int wm = (wid >> 1) * 32;       // 4 warps in m
    int wn = (wid & 1) * 64;        // 2 warps in n

    float acc[2][8][4];
    #pragma unroll
    for (int mt = 0; mt < 2; mt++)
        #pragma unroll
        for (int nt = 0; nt < 8; nt++)
            #pragma unroll
            for (int i = 0; i < 4; i++) acc[mt][nt][i] = 0.f;

    #pragma unroll 1
    for (int s = 0; s < NSTAGE; s++) {
        if (s < NSTAGE - 1) asm volatile("cp.async.wait_group 1;" ::: "memory");
        else                asm volatile("cp.async.wait_group 0;" ::: "memory");
        __syncthreads();

        if (s + 2 < NSTAGE) LOAD_STAGE((s + 2) % 3, (s + 2) * KC);

        const float* As = sm + (s % 3) * STG_FLOATS;
        const float* Bs = As + BM * LDS_PAD;

        #pragma unroll
        for (int kk = 0; kk < 4; kk++) {
            uint32_t a[2][4], b[8][2];
            #pragma unroll
            for (int mt = 0; mt < 2; mt++) {
                const uint32_t* ap = (const uint32_t*)(As + (wm + mt * 16 + g) * LDS_PAD + kk * 8 + tg);
                a[mt][0] = ap[0];
                a[mt][1] = ap[8 * LDS_PAD];
                a[mt][2] = ap[4];
                a[mt][3] = ap[8 * LDS_PAD + 4];
            }
            #pragma unroll
            for (int nt = 0; nt < 8; nt++) {
                const uint32_t* bp = (const uint32_t*)(Bs + (wn + nt * 8 + g) * LDS_PAD + kk * 8 + tg);
                b[nt][0] = bp[0];
                b[nt][1] = bp[4];
            }
            #pragma unroll
            for (int mt = 0; mt < 2; mt++)
                #pragma unroll
                for (int nt = 0; nt < 8; nt++)
                    mma_tf32(acc[mt][nt], a[mt], b[nt]);
        }
    }

    // ---------------- epilogue ----------------
    const float* brow = bias + (size_t)e * D + n0;
    float* Cb = (mode == 0) ? g_H : g_O;

    #pragma unroll
    for (int mt = 0; mt < 2; mt++) {
        #pragma unroll
        for (int rr = 0; rr < 2; rr++) {
            int m = m0 + wm + mt * 16 + rr * 8 + g;
            if (m >= ne) continue;
            float* crow = Cb + ((size_t)e * CAP + m) * D + n0;
            #pragma unroll
            for (int nt = 0; nt < 8; nt++) {
                int col = wn + nt * 8 + tg * 2;
                float v0 = acc[mt][nt][rr * 2 + 0] + brow[col];
                float v1 = acc[mt][nt][rr * 2 + 1] + brow[col + 1];
                if (mode == 0) {
                    v0 = round_tf32(fmaxf(v0, 0.f));   // pre-round H for pass 2
                    v1 = round_tf32(fmaxf(v1, 0.f));
                }
                float2 v = make_float2(v0, v1);
                *(float2*)(crow + col) = v;
            }
        }
    }
}

// ---------------- combine ----------------
__global__ void combine_kernel(float* __restrict__ y, int N)
{
    int token = blockIdx.x;
    if (token >= N) return;
    int   s0 = g_slot[token * 2 + 0];
    int   s1 = g_slot[token * 2 + 1];
    float w0 = g_wgt[token * 2 + 0];
    float w1 = g_wgt[token * 2 + 1];
    const float* o0 = g_O + (size_t)s0 * D;
    const float* o1 = g_O + (size_t)s1 * D;
    float* yr = y + (size_t)token * D;
    for (int i = threadIdx.x; i < D; i += blockDim.x)
        yr[i] = w0 * o0[i] + w1 * o1[i];
}

extern "C" void kernel_launch(void* const* d_in, const int* in_sizes, int n_in,
                              void* d_out, int out_size)
{
    const float* x  = (const float*)d_in[0];
    const float* gW = (const float*)d_in[1];
    const float* gb = (const float*)d_in[2];
    const float* w1 = (const float*)d_in[3];
    const float* b1 = (const float*)d_in[4];
    const float* w2 = (const float*)d_in[5];
    const float* b2 = (const float*)d_in[6];

    int N = in_sizes[0] / D;   // 4096

    float* y         = (float*)d_out;
    float* gate_prob = (float*)d_out + (size_t)N * D;

    static int smem_set = 0;
    if (!smem_set) {
        cudaFuncSetAttribute(expert_gemm_mma,
                             cudaFuncAttributeMaxDynamicSharedMemorySize, SMEM_BYTES);
        smem_set = 1;
    }

    zero_counts_kernel<<<1, 32>>>();
    round_w_kernel<<<1184, 256>>>(w1, w2);
    gate_kernel<<<N, 256>>>(x, gW, gb, gate_prob, N);

    dim3 grid(NMAX / BM, D / BN, E);   // 32 x 8 x 8, inactive tiles exit early
    expert_gemm_mma<<<grid, 256, SMEM_BYTES>>>(b1, 0);
    expert_gemm_mma<<<grid, 256, SMEM_BYTES>>>(b2, 1);

    combine_kernel<<<N, 256>>>(y, N);
}